// round 2
// baseline (speedup 1.0000x reference)
#include <cuda_runtime.h>

// ---------------------------------------------------------------------------
// OpticalFlowLoss fused kernel for GB300 (sm_103a)
// pred, gt: [B=8, T=8, C=3, H=256, W=256] fp32
// out: scalar fp32 loss
// ---------------------------------------------------------------------------

#define B_    8
#define T_    8
#define H_    256
#define W_    256
#define HW_   (H_ * W_)         // 65536
#define FRAME_STRIDE (3 * HW_)  // stride between frames (in floats)
#define NPAIRS (B_ * (T_ - 1))  // 56

#define TILE_W 64
#define TILE_H 16
#define HALO_W (TILE_W + 2)     // 66
#define HALO_H (TILE_H + 2)     // 18
#define SMEM_PITCH (HALO_W + 2) // 68, pad to dodge bank conflicts

#define EPSF 1e-3f

// total element count of the loss mean: B*(T-1)*2*H*W = 8*7*2*256*256
#define MEAN_COUNT 7340032.0

__device__ double g_accum;

__device__ __forceinline__ float gray3(float r, float g, float b) {
    return 0.2989f * r + 0.587f * g + 0.114f * b;
}

// gray value at (h,w) of the frame starting at img+base, zero outside bounds
__device__ __forceinline__ float grayAt(const float* __restrict__ img, int base,
                                        int h, int w) {
    if ((unsigned)h >= H_ || (unsigned)w >= W_) return 0.0f;
    int off = base + h * W_ + w;
    float r = __ldg(img + off);
    float g = __ldg(img + off + HW_);
    float b = __ldg(img + off + 2 * HW_);
    return gray3(r, g, b);
}

__global__ void zero_accum_kernel() {
    g_accum = 0.0;
}

__global__ __launch_bounds__(256, 8)
void flow_loss_kernel(const float* __restrict__ pred,
                      const float* __restrict__ gt) {
    const int pair = blockIdx.z;          // 0..55
    const int b = pair / (T_ - 1);
    const int t = pair % (T_ - 1);

    const int tileX = blockIdx.x * TILE_W;
    const int tileY = blockIdx.y * TILE_H;

    const int base1 = (b * T_ + t) * FRAME_STRIDE;       // frame t
    const int base2 = base1 + FRAME_STRIDE;              // frame t+1

    __shared__ float sP[HALO_H][SMEM_PITCH];  // pred gray, frame t, with halo
    __shared__ float sG[HALO_H][SMEM_PITCH];  // gt   gray, frame t, with halo

    // --- load halo tiles (grayscale computed on the fly, zero-padded) ---
    for (int i = threadIdx.x; i < HALO_H * HALO_W; i += blockDim.x) {
        int hy = i / HALO_W;
        int hx = i - hy * HALO_W;
        int gh = tileY + hy - 1;
        int gw = tileX + hx - 1;
        sP[hy][hx] = grayAt(pred, base1, gh, gw);
        sG[hy][hx] = grayAt(gt,   base1, gh, gw);
    }
    __syncthreads();

    float acc = 0.0f;

    #pragma unroll
    for (int k = 0; k < (TILE_W * TILE_H) / 256; ++k) {
        int i  = threadIdx.x + k * 256;
        int ly = i / TILE_W;
        int lx = i - ly * TILE_W;
        int h  = tileY + ly;
        int w  = tileX + lx;
        int off = h * W_ + w;

        // ---- pred flow ----
        float p00 = sP[ly][lx],   p01 = sP[ly][lx + 1],   p02 = sP[ly][lx + 2];
        float p10 = sP[ly+1][lx],                          p12 = sP[ly+1][lx + 2];
        float p20 = sP[ly+2][lx], p21 = sP[ly+2][lx + 1], p22 = sP[ly+2][lx + 2];
        float pc  = sP[ly+1][lx+1];

        float IxP = (p00 - p02) + 2.0f * (p10 - p12) + (p20 - p22);
        float IyP = (p00 + 2.0f * p01 + p02) - (p20 + 2.0f * p21 + p22);

        float pr2 = __ldg(pred + base2 + off);
        float pg2 = __ldg(pred + base2 + off + HW_);
        float pb2 = __ldg(pred + base2 + off + 2 * HW_);
        float ItP = gray3(pr2, pg2, pb2) - pc;

        float invP = 1.0f / (IxP * IxP + IyP * IyP + EPSF);
        float uP = -IxP * ItP * invP;
        float vP = -IyP * ItP * invP;

        // ---- gt flow ----
        float g00 = sG[ly][lx],   g01 = sG[ly][lx + 1],   g02 = sG[ly][lx + 2];
        float g10 = sG[ly+1][lx],                          g12 = sG[ly+1][lx + 2];
        float g20 = sG[ly+2][lx], g21 = sG[ly+2][lx + 1], g22 = sG[ly+2][lx + 2];
        float gc  = sG[ly+1][lx+1];

        float IxG = (g00 - g02) + 2.0f * (g10 - g12) + (g20 - g22);
        float IyG = (g00 + 2.0f * g01 + g02) - (g20 + 2.0f * g21 + g22);

        float gr2 = __ldg(gt + base2 + off);
        float gg2 = __ldg(gt + base2 + off + HW_);
        float gb2 = __ldg(gt + base2 + off + 2 * HW_);
        float ItG = gray3(gr2, gg2, gb2) - gc;

        float invG = 1.0f / (IxG * IxG + IyG * IyG + EPSF);
        float uG = -IxG * ItG * invG;
        float vG = -IyG * ItG * invG;

        // ---- motion magnitude (mean abs RGB diff of gt frames) ----
        float gr1 = __ldg(gt + base1 + off);
        float gg1 = __ldg(gt + base1 + off + HW_);
        float gb1 = __ldg(gt + base1 + off + 2 * HW_);
        float mm = (fabsf(gr2 - gr1) + fabsf(gg2 - gg1) + fabsf(gb2 - gb1))
                   * (1.0f / 3.0f);

        acc += (fabsf(uP - uG) + fabsf(vP - vG)) * mm;
    }

    // --- block reduction ---
    #pragma unroll
    for (int s = 16; s > 0; s >>= 1)
        acc += __shfl_xor_sync(0xFFFFFFFFu, acc, s);

    __shared__ float warpSum[8];
    int lane = threadIdx.x & 31;
    int wid  = threadIdx.x >> 5;
    if (lane == 0) warpSum[wid] = acc;
    __syncthreads();

    if (wid == 0) {
        float v = (lane < 8) ? warpSum[lane] : 0.0f;
        #pragma unroll
        for (int s = 4; s > 0; s >>= 1)
            v += __shfl_xor_sync(0xFFFFFFFFu, v, s);
        if (lane == 0)
            atomicAdd(&g_accum, (double)v);
    }
}

__global__ void finalize_kernel(float* __restrict__ out) {
    out[0] = (float)(g_accum / MEAN_COUNT);
}

extern "C" void kernel_launch(void* const* d_in, const int* in_sizes, int n_in,
                              void* d_out, int out_size) {
    const float* pred = (const float*)d_in[0];
    const float* gt   = (const float*)d_in[1];
    float* out = (float*)d_out;

    zero_accum_kernel<<<1, 1>>>();

    dim3 grid(W_ / TILE_W, H_ / TILE_H, NPAIRS);  // (4, 16, 56)
    flow_loss_kernel<<<grid, 256>>>(pred, gt);

    finalize_kernel<<<1, 1>>>(out);
}